// round 6
// baseline (speedup 1.0000x reference)
#include <cuda_runtime.h>
#include <cstdint>

#define NSPOT 50000
#define NGENE 2000
#define HID   64
#define NEDGE 800000
#define BN_EPS 1e-5f

// ---------------- device scratch (no allocation allowed) ----------------
__device__ float g_z[NSPOT * HID];        // raw z, later reused for u_nb
__device__ float g_uself[NSPOT * HID];    // relu(h@Ws1+bs1)
__device__ float g_agg[NSPOT * HID];      // neighbor raw sums
__device__ int   g_cnt[NSPOT];
__device__ float g_part[500 * 128];
__device__ float g_sc[HID];               // gamma * rstd
__device__ float g_sh[HID];               // beta - mean * gamma * rstd

// ---------------- tf32 helpers ------------------------------------------
__device__ __forceinline__ uint32_t f2tf(float f) {
    uint32_t r; asm("cvt.rna.tf32.f32 %0, %1;" : "=r"(r) : "f"(f)); return r;
}
__device__ __forceinline__ void mma8(float* c, const uint32_t* a, const uint32_t* b) {
    asm volatile(
        "mma.sync.aligned.m16n8k8.row.col.f32.tf32.tf32.f32 "
        "{%0,%1,%2,%3}, {%4,%5,%6,%7}, {%8,%9}, {%0,%1,%2,%3};"
        : "+f"(c[0]), "+f"(c[1]), "+f"(c[2]), "+f"(c[3])
        : "r"(a[0]), "r"(a[1]), "r"(a[2]), "r"(a[3]), "r"(b[0]), "r"(b[1]));
}
__device__ __forceinline__ void cpa16(uint32_t s, const void* g, bool pred) {
    int sz = pred ? 16 : 0;
    asm volatile("cp.async.cg.shared.global [%0], [%1], 16, %2;"
                 :: "r"(s), "l"(g), "r"(sz));
}

// ============ 3-stage cp.async TF32 GEMM (for K=2000) ====================
// BM=128, BN=64, BK=32.
__global__ __launch_bounds__(256)
void gemm1_db(const float* __restrict__ A, const float* __restrict__ B,
              const float* __restrict__ bias, float* __restrict__ C,
              int M, int N, int K)
{
    constexpr int BM = 128, BN = 64, BK = 32;
    constexpr int ASTR = BK + 4;     // 36
    constexpr int BSTR = BN + 8;     // 72
    constexpr int STAGE = BM * ASTR + BK * BSTR;   // words per stage
    extern __shared__ __align__(16) float smem1[];

    const int tid = threadIdx.x;
    const int lane = tid & 31, wid = tid >> 5;
    const int g = lane >> 2, tg = lane & 3;
    const int rowBase = blockIdx.y * BM;
    const int mW = (wid >> 1) * 32;
    const int nW = (wid & 1) * 32;

    float acc[2][4][4];
#pragma unroll
    for (int i = 0; i < 2; i++)
#pragma unroll
        for (int j = 0; j < 4; j++)
#pragma unroll
            for (int q = 0; q < 4; q++) acc[i][j][q] = 0.f;

    const int KT = (K + BK - 1) / BK;

    auto loadTiles = [&](int buf, int k0) {
        float* Ab = smem1 + buf * STAGE;
        float* Bb = Ab + BM * ASTR;
#pragma unroll
        for (int ii = 0; ii < 4; ii++) {
            int i = tid + ii * 256;
            int m = i >> 3, k4 = (i & 7) * 4;
            int r = rowBase + m, gk = k0 + k4;
            cpa16((uint32_t)__cvta_generic_to_shared(Ab + m * ASTR + k4),
                  A + (size_t)r * K + gk, (r < M) && (gk < K));
        }
#pragma unroll
        for (int ii = 0; ii < 2; ii++) {
            int i = tid + ii * 256;
            int kk = i >> 4, n4 = (i & 15) * 4;
            int gk = k0 + kk;
            cpa16((uint32_t)__cvta_generic_to_shared(Bb + kk * BSTR + n4),
                  B + (size_t)gk * N + n4, (gk < K) && (n4 < N));
        }
    };

    loadTiles(0, 0);
    asm volatile("cp.async.commit_group;");
    loadTiles(1, BK);
    asm volatile("cp.async.commit_group;");

    for (int kt = 0; kt < KT; kt++) {
        if (kt + 2 < KT) loadTiles((kt + 2) % 3, (kt + 2) * BK);
        asm volatile("cp.async.commit_group;");
        asm volatile("cp.async.wait_group 2;");
        __syncthreads();
        const float* Ab = smem1 + (kt % 3) * STAGE;
        const float* Bb = Ab + BM * ASTR;
#pragma unroll
        for (int ks = 0; ks < BK / 8; ks++) {
            uint32_t a[2][4], b[4][2];
#pragma unroll
            for (int i = 0; i < 2; i++) {
                int r0 = mW + i * 16 + g;
                a[i][0] = f2tf(Ab[r0 * ASTR + ks * 8 + tg]);
                a[i][1] = f2tf(Ab[(r0 + 8) * ASTR + ks * 8 + tg]);
                a[i][2] = f2tf(Ab[r0 * ASTR + ks * 8 + tg + 4]);
                a[i][3] = f2tf(Ab[(r0 + 8) * ASTR + ks * 8 + tg + 4]);
            }
#pragma unroll
            for (int j = 0; j < 4; j++) {
                b[j][0] = f2tf(Bb[(ks * 8 + tg) * BSTR + nW + j * 8 + g]);
                b[j][1] = f2tf(Bb[(ks * 8 + tg + 4) * BSTR + nW + j * 8 + g]);
            }
#pragma unroll
            for (int i = 0; i < 2; i++)
#pragma unroll
                for (int j = 0; j < 4; j++)
                    mma8(acc[i][j], a[i], b[j]);
        }
        __syncthreads();
    }

#pragma unroll
    for (int i = 0; i < 2; i++) {
        int r0 = rowBase + mW + i * 16 + g;
        int r1 = r0 + 8;
#pragma unroll
        for (int j = 0; j < 4; j++) {
            int c = nW + j * 8 + tg * 2;
            float bi0 = __ldg(bias + c), bi1 = __ldg(bias + c + 1);
            if (r0 < M)
                *reinterpret_cast<float2*>(C + (size_t)r0 * N + c) =
                    make_float2(acc[i][j][0] + bi0, acc[i][j][1] + bi1);
            if (r1 < M)
                *reinterpret_cast<float2*>(C + (size_t)r1 * N + c) =
                    make_float2(acc[i][j][2] + bi0, acc[i][j][3] + bi1);
        }
    }
}

// ======== generic TF32 GEMM (single-buffered, dynamic smem) ==============
// AMODE: 0 = none, 2 = per-row 1/cnt on A.
template<int BM, int BN, int BK, bool RELU, int AMODE>
__global__ __launch_bounds__(256)
void gemm_tf32(const float* __restrict__ A, const float* __restrict__ B,
               const float* __restrict__ bias, float* __restrict__ C,
               int M, int N, int K)
{
    constexpr int WARPS_N = BN / 32;
    constexpr int WARPS_M = 8 / WARPS_N;
    constexpr int WM = BM / WARPS_M;
    constexpr int MT = WM / 16;
    constexpr int NT = 4;
    constexpr int ASTR = BK + 4;
    constexpr int BSTR = BN + 8;

    extern __shared__ __align__(16) uint32_t dsm[];
    uint32_t* As = dsm;
    uint32_t* Bs = dsm + BM * ASTR;

    const int tid = threadIdx.x;
    const int lane = tid & 31, wid = tid >> 5;
    const int g = lane >> 2, tg = lane & 3;
    const int rowBase = blockIdx.y * BM;
    const int colBase = blockIdx.x * BN;
    const int mW = (wid / WARPS_N) * WM;
    const int nW = (wid % WARPS_N) * 32;

    float acc[MT][NT][4];
#pragma unroll
    for (int i = 0; i < MT; i++)
#pragma unroll
        for (int j = 0; j < NT; j++)
#pragma unroll
            for (int q = 0; q < 4; q++) acc[i][j][q] = 0.f;

    for (int k0 = 0; k0 < K; k0 += BK) {
#pragma unroll 2
        for (int i = tid; i < BM * (BK / 4); i += 256) {
            int m = i / (BK / 4), k4 = (i % (BK / 4)) * 4;
            int r = rowBase + m;
            uint4 v = {0u, 0u, 0u, 0u};
            if (r < M) {
                float4 f = *reinterpret_cast<const float4*>(A + (size_t)r * K + k0 + k4);
                if (AMODE == 2) {
                    float inv = 1.0f / fmaxf((float)__ldg(&g_cnt[r]), 1.0f);
                    f.x *= inv; f.y *= inv; f.z *= inv; f.w *= inv;
                }
                v.x = f2tf(f.x); v.y = f2tf(f.y); v.z = f2tf(f.z); v.w = f2tf(f.w);
            }
            *reinterpret_cast<uint4*>(&As[m * ASTR + k4]) = v;
        }
#pragma unroll 2
        for (int i = tid; i < BK * (BN / 4); i += 256) {
            int kk = i / (BN / 4), n4 = (i % (BN / 4)) * 4;
            int c = colBase + n4;
            uint4 v = {0u, 0u, 0u, 0u};
            if (c < N) {
                float4 f = *reinterpret_cast<const float4*>(B + (size_t)(k0 + kk) * N + c);
                v.x = f2tf(f.x); v.y = f2tf(f.y); v.z = f2tf(f.z); v.w = f2tf(f.w);
            }
            *reinterpret_cast<uint4*>(&Bs[kk * BSTR + n4]) = v;
        }
        __syncthreads();
#pragma unroll
        for (int ks = 0; ks < BK / 8; ks++) {
            uint32_t a[MT][4], b[NT][2];
#pragma unroll
            for (int i = 0; i < MT; i++) {
                int r0 = mW + i * 16 + g;
                a[i][0] = As[r0 * ASTR + ks * 8 + tg];
                a[i][1] = As[(r0 + 8) * ASTR + ks * 8 + tg];
                a[i][2] = As[r0 * ASTR + ks * 8 + tg + 4];
                a[i][3] = As[(r0 + 8) * ASTR + ks * 8 + tg + 4];
            }
#pragma unroll
            for (int j = 0; j < NT; j++) {
                b[j][0] = Bs[(ks * 8 + tg) * BSTR + nW + j * 8 + g];
                b[j][1] = Bs[(ks * 8 + tg + 4) * BSTR + nW + j * 8 + g];
            }
#pragma unroll
            for (int i = 0; i < MT; i++)
#pragma unroll
                for (int j = 0; j < NT; j++)
                    mma8(acc[i][j], a[i], b[j]);
        }
        __syncthreads();
    }

#pragma unroll
    for (int i = 0; i < MT; i++) {
        int r0 = rowBase + mW + i * 16 + g;
        int r1 = r0 + 8;
#pragma unroll
        for (int j = 0; j < NT; j++) {
            int c = colBase + nW + j * 8 + tg * 2;
            if (c >= N) continue;
            float bi0 = __ldg(bias + c), bi1 = __ldg(bias + c + 1);
            if (r0 < M) {
                float o0 = acc[i][j][0] + bi0, o1 = acc[i][j][1] + bi1;
                if (RELU) { o0 = fmaxf(o0, 0.f); o1 = fmaxf(o1, 0.f); }
                *reinterpret_cast<float2*>(C + (size_t)r0 * N + c) = make_float2(o0, o1);
            }
            if (r1 < M) {
                float o2 = acc[i][j][2] + bi0, o3 = acc[i][j][3] + bi1;
                if (RELU) { o2 = fmaxf(o2, 0.f); o3 = fmaxf(o3, 0.f); }
                *reinterpret_cast<float2*>(C + (size_t)r1 * N + c) = make_float2(o2, o3);
            }
        }
    }
}

// ======== fused encoder tail: BNReLU(z)@W2 -> h ; heads ; pos ============
// One CTA = 128 rows. Produces h (gmem), pos (gmem), u_self (g_uself).
__global__ __launch_bounds__(256)
void fused_enc(const float* __restrict__ z,
               const float* __restrict__ W2,  const float* __restrict__ b2,
               const float* __restrict__ Wp1, const float* __restrict__ bp1,
               const float* __restrict__ Ws1, const float* __restrict__ bs1,
               const float* __restrict__ Wp2, const float* __restrict__ bp2,
               float* __restrict__ h_out, float* __restrict__ pos_out,
               float* __restrict__ uself, int M)
{
    extern __shared__ __align__(16) uint32_t fsm[];
    uint32_t* Zs  = fsm;                  // 128 x 68 (A layout, tf32)
    uint32_t* W2s = Zs + 128 * 68;        // 64 x 72  (B layout)
    uint32_t* W13 = W2s + 64 * 72;        // 64 x 136 (B layout: Wp1|Ws1)
    float* upos = reinterpret_cast<float*>(W13);   // reuse: 128 x 65

    const int tid = threadIdx.x;
    const int lane = tid & 31, wid = tid >> 5;
    const int g = lane >> 2, tg = lane & 3;
    const int rowBase = blockIdx.x * 128;

    // --- fill Zs with tf32(relu(BN(z))) ---
#pragma unroll
    for (int ii = 0; ii < 8; ii++) {
        int i = tid + ii * 256;           // 128*16 = 2048
        int m = i >> 4, k4 = (i & 15) * 4;
        int r = rowBase + m;
        uint4 v = {0u, 0u, 0u, 0u};
        if (r < M) {
            float4 f = *reinterpret_cast<const float4*>(z + (size_t)r * HID + k4);
            f.x = fmaxf(fmaf(f.x, g_sc[k4+0], g_sh[k4+0]), 0.f);
            f.y = fmaxf(fmaf(f.y, g_sc[k4+1], g_sh[k4+1]), 0.f);
            f.z = fmaxf(fmaf(f.z, g_sc[k4+2], g_sh[k4+2]), 0.f);
            f.w = fmaxf(fmaf(f.w, g_sc[k4+3], g_sh[k4+3]), 0.f);
            v.x = f2tf(f.x); v.y = f2tf(f.y); v.z = f2tf(f.z); v.w = f2tf(f.w);
        }
        *reinterpret_cast<uint4*>(&Zs[m * 68 + k4]) = v;
    }
    // --- fill W2s ---
#pragma unroll
    for (int ii = 0; ii < 4; ii++) {
        int i = tid + ii * 256;           // 64*16 = 1024
        int kk = i >> 4, n4 = (i & 15) * 4;
        float4 f = *reinterpret_cast<const float4*>(W2 + kk * HID + n4);
        uint4 v; v.x = f2tf(f.x); v.y = f2tf(f.y); v.z = f2tf(f.z); v.w = f2tf(f.w);
        *reinterpret_cast<uint4*>(&W2s[kk * 72 + n4]) = v;
    }
    // --- fill W13 = [Wp1 | Ws1] ---
#pragma unroll
    for (int ii = 0; ii < 8; ii++) {
        int i = tid + ii * 256;           // 64*32 = 2048
        int kk = i >> 5, n4 = (i & 31) * 4;
        const float* src = (n4 < 64) ? (Wp1 + kk * HID + n4) : (Ws1 + kk * HID + n4 - 64);
        float4 f = *reinterpret_cast<const float4*>(src);
        uint4 v; v.x = f2tf(f.x); v.y = f2tf(f.y); v.z = f2tf(f.z); v.w = f2tf(f.w);
        *reinterpret_cast<uint4*>(&W13[kk * 136 + n4]) = v;
    }
    __syncthreads();

    // --- stage 1: h = Zs @ W2 + b2  (warps: 4 along M, 2 along N) ---
    {
        const int mW = (wid >> 1) * 32;
        const int nW = (wid & 1) * 32;
        float acc[2][4][4];
#pragma unroll
        for (int i = 0; i < 2; i++)
#pragma unroll
            for (int j = 0; j < 4; j++)
#pragma unroll
                for (int q = 0; q < 4; q++) acc[i][j][q] = 0.f;
#pragma unroll
        for (int ks = 0; ks < 8; ks++) {
            uint32_t a[2][4], b[4][2];
#pragma unroll
            for (int i = 0; i < 2; i++) {
                int r0 = mW + i * 16 + g;
                a[i][0] = Zs[r0 * 68 + ks * 8 + tg];
                a[i][1] = Zs[(r0 + 8) * 68 + ks * 8 + tg];
                a[i][2] = Zs[r0 * 68 + ks * 8 + tg + 4];
                a[i][3] = Zs[(r0 + 8) * 68 + ks * 8 + tg + 4];
            }
#pragma unroll
            for (int j = 0; j < 4; j++) {
                b[j][0] = W2s[(ks * 8 + tg) * 72 + nW + j * 8 + g];
                b[j][1] = W2s[(ks * 8 + tg + 4) * 72 + nW + j * 8 + g];
            }
#pragma unroll
            for (int i = 0; i < 2; i++)
#pragma unroll
                for (int j = 0; j < 4; j++)
                    mma8(acc[i][j], a[i], b[j]);
        }
        __syncthreads();   // all Zs reads done before overwrite
        // epilogue: h -> gmem + back into Zs (tf32, A layout)
#pragma unroll
        for (int i = 0; i < 2; i++) {
            int lr0 = mW + i * 16 + g, lr1 = lr0 + 8;
            int r0 = rowBase + lr0, r1 = rowBase + lr1;
#pragma unroll
            for (int j = 0; j < 4; j++) {
                int c = nW + j * 8 + tg * 2;
                float bi0 = __ldg(b2 + c), bi1 = __ldg(b2 + c + 1);
                float h0 = acc[i][j][0] + bi0, h1 = acc[i][j][1] + bi1;
                float h2 = acc[i][j][2] + bi0, h3 = acc[i][j][3] + bi1;
                Zs[lr0 * 68 + c] = f2tf(h0); Zs[lr0 * 68 + c + 1] = f2tf(h1);
                Zs[lr1 * 68 + c] = f2tf(h2); Zs[lr1 * 68 + c + 1] = f2tf(h3);
                if (r0 < M)
                    *reinterpret_cast<float2*>(h_out + (size_t)r0 * HID + c) = make_float2(h0, h1);
                if (r1 < M)
                    *reinterpret_cast<float2*>(h_out + (size_t)r1 * HID + c) = make_float2(h2, h3);
            }
        }
    }
    __syncthreads();

    // --- stage 2: [u_pos | u_self] = h @ [Wp1|Ws1]  (warps: 2 M x 4 N) ---
    {
        const int mW = (wid >> 2) * 64;
        const int nW = (wid & 3) * 32;
        float acc[4][4][4];
#pragma unroll
        for (int i = 0; i < 4; i++)
#pragma unroll
            for (int j = 0; j < 4; j++)
#pragma unroll
                for (int q = 0; q < 4; q++) acc[i][j][q] = 0.f;
#pragma unroll
        for (int ks = 0; ks < 8; ks++) {
            uint32_t a[4][4], b[4][2];
#pragma unroll
            for (int i = 0; i < 4; i++) {
                int r0 = mW + i * 16 + g;
                a[i][0] = Zs[r0 * 68 + ks * 8 + tg];
                a[i][1] = Zs[(r0 + 8) * 68 + ks * 8 + tg];
                a[i][2] = Zs[r0 * 68 + ks * 8 + tg + 4];
                a[i][3] = Zs[(r0 + 8) * 68 + ks * 8 + tg + 4];
            }
#pragma unroll
            for (int j = 0; j < 4; j++) {
                b[j][0] = W13[(ks * 8 + tg) * 136 + nW + j * 8 + g];
                b[j][1] = W13[(ks * 8 + tg + 4) * 136 + nW + j * 8 + g];
            }
#pragma unroll
            for (int i = 0; i < 4; i++)
#pragma unroll
                for (int j = 0; j < 4; j++)
                    mma8(acc[i][j], a[i], b[j]);
        }
        __syncthreads();   // W13 reads done -> safe to reuse as upos
        // epilogue: cols<64 -> relu into upos smem; cols>=64 -> relu -> g_uself
#pragma unroll
        for (int i = 0; i < 4; i++) {
            int lr0 = mW + i * 16 + g, lr1 = lr0 + 8;
            int r0 = rowBase + lr0, r1 = rowBase + lr1;
#pragma unroll
            for (int j = 0; j < 4; j++) {
                int c = nW + j * 8 + tg * 2;
                if (c < 64) {
                    float bi0 = __ldg(bp1 + c), bi1 = __ldg(bp1 + c + 1);
                    upos[lr0 * 65 + c]     = fmaxf(acc[i][j][0] + bi0, 0.f);
                    upos[lr0 * 65 + c + 1] = fmaxf(acc[i][j][1] + bi1, 0.f);
                    upos[lr1 * 65 + c]     = fmaxf(acc[i][j][2] + bi0, 0.f);
                    upos[lr1 * 65 + c + 1] = fmaxf(acc[i][j][3] + bi1, 0.f);
                } else {
                    int cc = c - 64;
                    float bi0 = __ldg(bs1 + cc), bi1 = __ldg(bs1 + cc + 1);
                    float o0 = fmaxf(acc[i][j][0] + bi0, 0.f);
                    float o1 = fmaxf(acc[i][j][1] + bi1, 0.f);
                    float o2 = fmaxf(acc[i][j][2] + bi0, 0.f);
                    float o3 = fmaxf(acc[i][j][3] + bi1, 0.f);
                    if (r0 < M)
                        *reinterpret_cast<float2*>(uself + (size_t)r0 * HID + cc) = make_float2(o0, o1);
                    if (r1 < M)
                        *reinterpret_cast<float2*>(uself + (size_t)r1 * HID + cc) = make_float2(o2, o3);
                }
            }
        }
    }
    __syncthreads();

    // --- pos head: pos = upos @ Wp2 + bp2 ---
    if (tid < 128) {
        int r = rowBase + tid;
        if (r < M) {
            float p0 = __ldg(bp2), p1 = __ldg(bp2 + 1);
#pragma unroll
            for (int k = 0; k < HID; k++) {
                float v = upos[tid * 65 + k];
                p0 = fmaf(v, __ldg(Wp2 + k * 2), p0);
                p1 = fmaf(v, __ldg(Wp2 + k * 2 + 1), p1);
            }
            pos_out[(size_t)r * 2]     = p0;
            pos_out[(size_t)r * 2 + 1] = p1;
        }
    }
}

// ---------------- BatchNorm statistics (deterministic 2-stage) ----------
__global__ void bn_stage1(const float* __restrict__ z)
{
    const int c = threadIdx.x;
    const int b = blockIdx.x;
    const int r0 = b * 100;
    float s = 0.f, ss = 0.f;
    for (int r = r0; r < r0 + 100; r++) {
        float v = z[(size_t)r * HID + c];
        s += v; ss += v * v;
    }
    g_part[b * 128 + c] = s;
    g_part[b * 128 + 64 + c] = ss;
}

__global__ void bn_stage2(const float* __restrict__ gamma, const float* __restrict__ beta)
{
    const int c = threadIdx.x;
    float s = 0.f, ss = 0.f;
    for (int b = 0; b < 500; b++) {
        s += g_part[b * 128 + c];
        ss += g_part[b * 128 + 64 + c];
    }
    float mu = s / (float)NSPOT;
    float var = ss / (float)NSPOT - mu * mu;
    float rstd = rsqrtf(var + BN_EPS);
    float sc = gamma[c] * rstd;
    g_sc[c] = sc;
    g_sh[c] = beta[c] - mu * sc;
}

// ---------------- edge aggregation ---------------------------------------
__global__ void zero_scratch()
{
    int i = blockIdx.x * blockDim.x + threadIdx.x;
    if (i < NSPOT * HID) g_agg[i] = 0.f;
    if (i < NSPOT) g_cnt[i] = 0;
}

__global__ void scatter_h(const float* __restrict__ h, const int* __restrict__ ei)
{
    long t = (long)blockIdx.x * blockDim.x + threadIdx.x;
    if (t >= (long)NEDGE * 16) return;
    int e = (int)(t >> 4), p = (int)(t & 15);
    int src = __ldg(ei + e);
    int dst = __ldg(ei + NEDGE + e);
    float4 v = *reinterpret_cast<const float4*>(h + (size_t)src * HID + p * 4);
    float* a = g_agg + (size_t)dst * HID + p * 4;
    if (p == 0) atomicAdd(&g_cnt[dst], 1);
    asm volatile("red.global.add.v4.f32 [%0], {%1,%2,%3,%4};"
                 :: "l"(a), "f"(v.x), "f"(v.y), "f"(v.z), "f"(v.w) : "memory");
}

// ---------------- launch ---------------------------------------------------
extern "C" void kernel_launch(void* const* d_in, const int* in_sizes, int n_in,
                              void* d_out, int out_size)
{
    const float* x     = (const float*)d_in[0];
    const int*   ei    = (const int*)  d_in[1];
    const float* W1    = (const float*)d_in[2];
    const float* b1    = (const float*)d_in[3];
    const float* gamma = (const float*)d_in[4];
    const float* beta  = (const float*)d_in[5];
    const float* W2    = (const float*)d_in[6];
    const float* b2    = (const float*)d_in[7];
    const float* Wp1   = (const float*)d_in[8];
    const float* bp1   = (const float*)d_in[9];
    const float* Wp2   = (const float*)d_in[10];
    const float* bp2   = (const float*)d_in[11];
    const float* Ws1   = (const float*)d_in[12];
    const float* bs1   = (const float*)d_in[13];
    const float* Ws2   = (const float*)d_in[14];
    const float* bs2   = (const float*)d_in[15];
    const float* We1   = (const float*)d_in[16];
    const float* be1   = (const float*)d_in[17];
    const float* We2   = (const float*)d_in[18];
    const float* be2   = (const float*)d_in[19];

    float* out = (float*)d_out;
    float* h_out   = out;
    float* pos_out = out + (size_t)NSPOT * HID;
    float* xs_out  = pos_out + (size_t)NSPOT * 2;
    float* xn_out  = xs_out + (size_t)NSPOT * NGENE;

    float* zp;   cudaGetSymbolAddress((void**)&zp, g_z);
    float* usp;  cudaGetSymbolAddress((void**)&usp, g_uself);
    float* aggp; cudaGetSymbolAddress((void**)&aggp, g_agg);

    const int MB = (NSPOT + 127) / 128;   // 391
    dim3 gN64(1, MB);
    dim3 gBig((NGENE + 127) / 128, MB);

    constexpr int SMEM1 = 3 * (128 * 36 + 32 * 72) * 4;                 // 82944
    constexpr int SMEMF = (128 * 68 + 64 * 72 + 64 * 136) * 4;          // 88064
    constexpr int SMEMB = (128 * 68 + 64 * 136) * 4;                    // 69632
    constexpr int SMEMS = (128 * 36 + 32 * 72) * 4;                     // 27648
    cudaFuncSetAttribute(gemm1_db, cudaFuncAttributeMaxDynamicSharedMemorySize, SMEM1);
    cudaFuncSetAttribute(fused_enc, cudaFuncAttributeMaxDynamicSharedMemorySize, SMEMF);
    cudaFuncSetAttribute(gemm_tf32<128, 128, 64, false, 0>,
                         cudaFuncAttributeMaxDynamicSharedMemorySize, SMEMB);
    cudaFuncSetAttribute(gemm_tf32<128, 64, 32, true, 2>,
                         cudaFuncAttributeMaxDynamicSharedMemorySize, SMEMS);

    // forked side stream for the scatter chain
    cudaStream_t s2;
    cudaStreamCreateWithFlags(&s2, cudaStreamNonBlocking);
    cudaEvent_t evFork, evEnc, evJoin;
    cudaEventCreateWithFlags(&evFork, cudaEventDisableTiming);
    cudaEventCreateWithFlags(&evEnc, cudaEventDisableTiming);
    cudaEventCreateWithFlags(&evJoin, cudaEventDisableTiming);

    // fork: zero g_agg/g_cnt in parallel with the encoder
    cudaEventRecord(evFork, 0);
    cudaStreamWaitEvent(s2, evFork, 0);
    zero_scratch<<<(NSPOT * HID + 255) / 256, 256, 0, s2>>>();

    // main: encoder
    gemm1_db<<<gN64, 256, SMEM1>>>(x, W1, b1, zp, NSPOT, HID, NGENE);
    bn_stage1<<<500, 64>>>(zp);
    bn_stage2<<<1, 64>>>(gamma, beta);
    fused_enc<<<MB, 256, SMEMF>>>(zp, W2, b2, Wp1, bp1, Ws1, bs1, Wp2, bp2,
                                  h_out, pos_out, usp, NSPOT);
    cudaEventRecord(evEnc, 0);

    // main: xs = u_self @ Ws2 + bs2  (6th launch -> ncu capture)
    gemm_tf32<128, 128, 64, false, 0><<<gBig, 256, SMEMB>>>(usp, Ws2, bs2, xs_out,
                                                            NSPOT, NGENE, HID);

    // side: scatter -> We1 MLP -> xn GEMM
    cudaStreamWaitEvent(s2, evEnc, 0);
    {
        long tot = (long)NEDGE * 16;
        scatter_h<<<(int)((tot + 255) / 256), 256, 0, s2>>>(h_out, ei);
    }
    gemm_tf32<128, 64, 32, true, 2><<<gN64, 256, SMEMS, s2>>>(aggp, We1, be1, zp,
                                                              NSPOT, HID, HID);
    gemm_tf32<128, 128, 64, false, 0><<<gBig, 256, SMEMB, s2>>>(zp, We2, be2, xn_out,
                                                                NSPOT, NGENE, HID);
    cudaEventRecord(evJoin, s2);
    cudaStreamWaitEvent(0, evJoin, 0);

    (void)in_sizes; (void)n_in; (void)out_size;
}

// round 7
// speedup vs baseline: 1.4364x; 1.4364x over previous
#include <cuda_runtime.h>
#include <cstdint>

#define NSPOT 50000
#define NGENE 2000
#define HID   64
#define NEDGE 800000
#define BN_EPS 1e-5f

// ---------------- device scratch (no allocation allowed) ----------------
__device__ float g_z[NSPOT * HID];        // raw z, later reused for u_nb
__device__ float g_uself[NSPOT * HID];    // relu(h@Ws1+bs1)
__device__ float g_agg[NSPOT * HID];      // neighbor raw sums
__device__ int   g_cnt[NSPOT];
__device__ float g_part[500 * 128];
__device__ float g_sc[HID];               // gamma * rstd
__device__ float g_sh[HID];               // beta - mean * gamma * rstd

// ---------------- tf32 helpers ------------------------------------------
__device__ __forceinline__ uint32_t f2tf(float f) {
    uint32_t r; asm("cvt.rna.tf32.f32 %0, %1;" : "=r"(r) : "f"(f)); return r;
}
__device__ __forceinline__ void mma8(float* c, const uint32_t* a, const uint32_t* b) {
    asm volatile(
        "mma.sync.aligned.m16n8k8.row.col.f32.tf32.tf32.f32 "
        "{%0,%1,%2,%3}, {%4,%5,%6,%7}, {%8,%9}, {%0,%1,%2,%3};"
        : "+f"(c[0]), "+f"(c[1]), "+f"(c[2]), "+f"(c[3])
        : "r"(a[0]), "r"(a[1]), "r"(a[2]), "r"(a[3]), "r"(b[0]), "r"(b[1]));
}
__device__ __forceinline__ void cpa16(uint32_t s, const void* g, bool pred) {
    int sz = pred ? 16 : 0;
    asm volatile("cp.async.cg.shared.global [%0], [%1], 16, %2;"
                 :: "r"(s), "l"(g), "r"(sz));
}

// ============ double-buffered cp.async TF32 GEMM (for K=2000) ============
// BM=128, BN=64, BK=32.  (round-5 proven version)
__global__ __launch_bounds__(256)
void gemm1_db(const float* __restrict__ A, const float* __restrict__ B,
              const float* __restrict__ bias, float* __restrict__ C,
              int M, int N, int K)
{
    constexpr int BM = 128, BN = 64, BK = 32;
    constexpr int ASTR = BK + 4;     // 36
    constexpr int BSTR = BN + 8;     // 72
    extern __shared__ float smem[];
    float* Asf = smem;                         // [2][BM*ASTR]
    float* Bsf = smem + 2 * BM * ASTR;         // [2][BK*BSTR]

    const int tid = threadIdx.x;
    const int lane = tid & 31, wid = tid >> 5;
    const int g = lane >> 2, tg = lane & 3;
    const int rowBase = blockIdx.y * BM;
    const int mW = (wid >> 1) * 32;
    const int nW = (wid & 1) * 32;

    float acc[2][4][4];
#pragma unroll
    for (int i = 0; i < 2; i++)
#pragma unroll
        for (int j = 0; j < 4; j++)
#pragma unroll
            for (int q = 0; q < 4; q++) acc[i][j][q] = 0.f;

    const int KT = (K + BK - 1) / BK;

    auto loadTiles = [&](int buf, int k0) {
        float* Ab = Asf + buf * BM * ASTR;
        float* Bb = Bsf + buf * BK * BSTR;
#pragma unroll
        for (int ii = 0; ii < 4; ii++) {
            int i = tid + ii * 256;
            int m = i >> 3, k4 = (i & 7) * 4;
            int r = rowBase + m, gk = k0 + k4;
            cpa16((uint32_t)__cvta_generic_to_shared(Ab + m * ASTR + k4),
                  A + (size_t)r * K + gk, (r < M) && (gk < K));
        }
#pragma unroll
        for (int ii = 0; ii < 2; ii++) {
            int i = tid + ii * 256;
            int kk = i >> 4, n4 = (i & 15) * 4;
            int gk = k0 + kk;
            cpa16((uint32_t)__cvta_generic_to_shared(Bb + kk * BSTR + n4),
                  B + (size_t)gk * N + n4, (gk < K) && (n4 < N));
        }
    };

    loadTiles(0, 0);
    asm volatile("cp.async.commit_group;");
    int buf = 0;
    for (int kt = 0; kt < KT; kt++) {
        if (kt + 1 < KT) loadTiles(buf ^ 1, (kt + 1) * BK);
        asm volatile("cp.async.commit_group;");
        asm volatile("cp.async.wait_group 1;");
        __syncthreads();
        const float* Ab = Asf + buf * BM * ASTR;
        const float* Bb = Bsf + buf * BK * BSTR;
#pragma unroll
        for (int ks = 0; ks < BK / 8; ks++) {
            uint32_t a[2][4], b[4][2];
#pragma unroll
            for (int i = 0; i < 2; i++) {
                int r0 = mW + i * 16 + g;
                a[i][0] = f2tf(Ab[r0 * ASTR + ks * 8 + tg]);
                a[i][1] = f2tf(Ab[(r0 + 8) * ASTR + ks * 8 + tg]);
                a[i][2] = f2tf(Ab[r0 * ASTR + ks * 8 + tg + 4]);
                a[i][3] = f2tf(Ab[(r0 + 8) * ASTR + ks * 8 + tg + 4]);
            }
#pragma unroll
            for (int j = 0; j < 4; j++) {
                b[j][0] = f2tf(Bb[(ks * 8 + tg) * BSTR + nW + j * 8 + g]);
                b[j][1] = f2tf(Bb[(ks * 8 + tg + 4) * BSTR + nW + j * 8 + g]);
            }
#pragma unroll
            for (int i = 0; i < 2; i++)
#pragma unroll
                for (int j = 0; j < 4; j++)
                    mma8(acc[i][j], a[i], b[j]);
        }
        __syncthreads();
        buf ^= 1;
    }

#pragma unroll
    for (int i = 0; i < 2; i++) {
        int r0 = rowBase + mW + i * 16 + g;
        int r1 = r0 + 8;
#pragma unroll
        for (int j = 0; j < 4; j++) {
            int c = nW + j * 8 + tg * 2;
            float bi0 = __ldg(bias + c), bi1 = __ldg(bias + c + 1);
            if (r0 < M)
                *reinterpret_cast<float2*>(C + (size_t)r0 * N + c) =
                    make_float2(acc[i][j][0] + bi0, acc[i][j][1] + bi1);
            if (r1 < M)
                *reinterpret_cast<float2*>(C + (size_t)r1 * N + c) =
                    make_float2(acc[i][j][2] + bi0, acc[i][j][3] + bi1);
        }
    }
}

// ======== generic TF32 GEMM (single-buffered, static smem) ===============
// AMODE: 0 = none, 2 = per-row 1/cnt on A.  (round-5 proven version)
template<int BM, int BN, int BK, bool RELU, int AMODE>
__global__ __launch_bounds__(256)
void gemm_tf32(const float* __restrict__ A, const float* __restrict__ B,
               const float* __restrict__ bias, float* __restrict__ C,
               int M, int N, int K)
{
    constexpr int WARPS_N = BN / 32;
    constexpr int WARPS_M = 8 / WARPS_N;
    constexpr int WM = BM / WARPS_M;
    constexpr int MT = WM / 16;
    constexpr int NT = 4;
    constexpr int ASTR = BK + 4;
    constexpr int BSTR = BN + 8;

    __shared__ __align__(16) uint32_t As[BM * ASTR];
    __shared__ __align__(16) uint32_t Bs[BK * BSTR];

    const int tid = threadIdx.x;
    const int lane = tid & 31, wid = tid >> 5;
    const int g = lane >> 2, tg = lane & 3;
    const int rowBase = blockIdx.y * BM;
    const int colBase = blockIdx.x * BN;
    const int mW = (wid / WARPS_N) * WM;
    const int nW = (wid % WARPS_N) * 32;

    float acc[MT][NT][4];
#pragma unroll
    for (int i = 0; i < MT; i++)
#pragma unroll
        for (int j = 0; j < NT; j++)
#pragma unroll
            for (int q = 0; q < 4; q++) acc[i][j][q] = 0.f;

    for (int k0 = 0; k0 < K; k0 += BK) {
#pragma unroll 2
        for (int i = tid; i < BM * (BK / 4); i += 256) {
            int m = i / (BK / 4), k4 = (i % (BK / 4)) * 4;
            int r = rowBase + m;
            uint4 v = {0u, 0u, 0u, 0u};
            if (r < M) {
                float4 f = *reinterpret_cast<const float4*>(A + (size_t)r * K + k0 + k4);
                if (AMODE == 2) {
                    float inv = 1.0f / fmaxf((float)__ldg(&g_cnt[r]), 1.0f);
                    f.x *= inv; f.y *= inv; f.z *= inv; f.w *= inv;
                }
                v.x = f2tf(f.x); v.y = f2tf(f.y); v.z = f2tf(f.z); v.w = f2tf(f.w);
            }
            *reinterpret_cast<uint4*>(&As[m * ASTR + k4]) = v;
        }
#pragma unroll 2
        for (int i = tid; i < BK * (BN / 4); i += 256) {
            int kk = i / (BN / 4), n4 = (i % (BN / 4)) * 4;
            int c = colBase + n4;
            uint4 v = {0u, 0u, 0u, 0u};
            if (c < N) {
                float4 f = *reinterpret_cast<const float4*>(B + (size_t)(k0 + kk) * N + c);
                v.x = f2tf(f.x); v.y = f2tf(f.y); v.z = f2tf(f.z); v.w = f2tf(f.w);
            }
            *reinterpret_cast<uint4*>(&Bs[kk * BSTR + n4]) = v;
        }
        __syncthreads();
#pragma unroll
        for (int ks = 0; ks < BK / 8; ks++) {
            uint32_t a[MT][4], b[NT][2];
#pragma unroll
            for (int i = 0; i < MT; i++) {
                int r0 = mW + i * 16 + g;
                a[i][0] = As[r0 * ASTR + ks * 8 + tg];
                a[i][1] = As[(r0 + 8) * ASTR + ks * 8 + tg];
                a[i][2] = As[r0 * ASTR + ks * 8 + tg + 4];
                a[i][3] = As[(r0 + 8) * ASTR + ks * 8 + tg + 4];
            }
#pragma unroll
            for (int j = 0; j < NT; j++) {
                b[j][0] = Bs[(ks * 8 + tg) * BSTR + nW + j * 8 + g];
                b[j][1] = Bs[(ks * 8 + tg + 4) * BSTR + nW + j * 8 + g];
            }
#pragma unroll
            for (int i = 0; i < MT; i++)
#pragma unroll
                for (int j = 0; j < NT; j++)
                    mma8(acc[i][j], a[i], b[j]);
        }
        __syncthreads();
    }

#pragma unroll
    for (int i = 0; i < MT; i++) {
        int r0 = rowBase + mW + i * 16 + g;
        int r1 = r0 + 8;
#pragma unroll
        for (int j = 0; j < NT; j++) {
            int c = colBase + nW + j * 8 + tg * 2;
            if (c >= N) continue;
            float bi0 = __ldg(bias + c), bi1 = __ldg(bias + c + 1);
            if (r0 < M) {
                float o0 = acc[i][j][0] + bi0, o1 = acc[i][j][1] + bi1;
                if (RELU) { o0 = fmaxf(o0, 0.f); o1 = fmaxf(o1, 0.f); }
                *reinterpret_cast<float2*>(C + (size_t)r0 * N + c) = make_float2(o0, o1);
            }
            if (r1 < M) {
                float o2 = acc[i][j][2] + bi0, o3 = acc[i][j][3] + bi1;
                if (RELU) { o2 = fmaxf(o2, 0.f); o3 = fmaxf(o3, 0.f); }
                *reinterpret_cast<float2*>(C + (size_t)r1 * N + c) = make_float2(o2, o3);
            }
        }
    }
}

// ======== fused encoder tail: BNReLU(z)@W2 -> h ; heads ; pos ============
__global__ __launch_bounds__(256)
void fused_enc(const float* __restrict__ z,
               const float* __restrict__ W2,  const float* __restrict__ b2,
               const float* __restrict__ Wp1, const float* __restrict__ bp1,
               const float* __restrict__ Ws1, const float* __restrict__ bs1,
               const float* __restrict__ Wp2, const float* __restrict__ bp2,
               float* __restrict__ h_out, float* __restrict__ pos_out,
               float* __restrict__ uself, int M)
{
    extern __shared__ __align__(16) uint32_t fsm[];
    uint32_t* Zs  = fsm;                  // 128 x 68 (A layout, tf32)
    uint32_t* W2s = Zs + 128 * 68;        // 64 x 72  (B layout)
    uint32_t* W13 = W2s + 64 * 72;        // 64 x 136 (B layout: Wp1|Ws1)
    float* upos = reinterpret_cast<float*>(W13);   // reuse: 128 x 65

    const int tid = threadIdx.x;
    const int lane = tid & 31, wid = tid >> 5;
    const int g = lane >> 2, tg = lane & 3;
    const int rowBase = blockIdx.x * 128;

#pragma unroll
    for (int ii = 0; ii < 8; ii++) {
        int i = tid + ii * 256;
        int m = i >> 4, k4 = (i & 15) * 4;
        int r = rowBase + m;
        uint4 v = {0u, 0u, 0u, 0u};
        if (r < M) {
            float4 f = *reinterpret_cast<const float4*>(z + (size_t)r * HID + k4);
            f.x = fmaxf(fmaf(f.x, g_sc[k4+0], g_sh[k4+0]), 0.f);
            f.y = fmaxf(fmaf(f.y, g_sc[k4+1], g_sh[k4+1]), 0.f);
            f.z = fmaxf(fmaf(f.z, g_sc[k4+2], g_sh[k4+2]), 0.f);
            f.w = fmaxf(fmaf(f.w, g_sc[k4+3], g_sh[k4+3]), 0.f);
            v.x = f2tf(f.x); v.y = f2tf(f.y); v.z = f2tf(f.z); v.w = f2tf(f.w);
        }
        *reinterpret_cast<uint4*>(&Zs[m * 68 + k4]) = v;
    }
#pragma unroll
    for (int ii = 0; ii < 4; ii++) {
        int i = tid + ii * 256;
        int kk = i >> 4, n4 = (i & 15) * 4;
        float4 f = *reinterpret_cast<const float4*>(W2 + kk * HID + n4);
        uint4 v; v.x = f2tf(f.x); v.y = f2tf(f.y); v.z = f2tf(f.z); v.w = f2tf(f.w);
        *reinterpret_cast<uint4*>(&W2s[kk * 72 + n4]) = v;
    }
#pragma unroll
    for (int ii = 0; ii < 8; ii++) {
        int i = tid + ii * 256;
        int kk = i >> 5, n4 = (i & 31) * 4;
        const float* src = (n4 < 64) ? (Wp1 + kk * HID + n4) : (Ws1 + kk * HID + n4 - 64);
        float4 f = *reinterpret_cast<const float4*>(src);
        uint4 v; v.x = f2tf(f.x); v.y = f2tf(f.y); v.z = f2tf(f.z); v.w = f2tf(f.w);
        *reinterpret_cast<uint4*>(&W13[kk * 136 + n4]) = v;
    }
    __syncthreads();

    // --- stage 1: h = Zs @ W2 + b2 ---
    {
        const int mW = (wid >> 1) * 32;
        const int nW = (wid & 1) * 32;
        float acc[2][4][4];
#pragma unroll
        for (int i = 0; i < 2; i++)
#pragma unroll
            for (int j = 0; j < 4; j++)
#pragma unroll
                for (int q = 0; q < 4; q++) acc[i][j][q] = 0.f;
#pragma unroll
        for (int ks = 0; ks < 8; ks++) {
            uint32_t a[2][4], b[4][2];
#pragma unroll
            for (int i = 0; i < 2; i++) {
                int r0 = mW + i * 16 + g;
                a[i][0] = Zs[r0 * 68 + ks * 8 + tg];
                a[i][1] = Zs[(r0 + 8) * 68 + ks * 8 + tg];
                a[i][2] = Zs[r0 * 68 + ks * 8 + tg + 4];
                a[i][3] = Zs[(r0 + 8) * 68 + ks * 8 + tg + 4];
            }
#pragma unroll
            for (int j = 0; j < 4; j++) {
                b[j][0] = W2s[(ks * 8 + tg) * 72 + nW + j * 8 + g];
                b[j][1] = W2s[(ks * 8 + tg + 4) * 72 + nW + j * 8 + g];
            }
#pragma unroll
            for (int i = 0; i < 2; i++)
#pragma unroll
                for (int j = 0; j < 4; j++)
                    mma8(acc[i][j], a[i], b[j]);
        }
        __syncthreads();
#pragma unroll
        for (int i = 0; i < 2; i++) {
            int lr0 = mW + i * 16 + g, lr1 = lr0 + 8;
            int r0 = rowBase + lr0, r1 = rowBase + lr1;
#pragma unroll
            for (int j = 0; j < 4; j++) {
                int c = nW + j * 8 + tg * 2;
                float bi0 = __ldg(b2 + c), bi1 = __ldg(b2 + c + 1);
                float h0 = acc[i][j][0] + bi0, h1 = acc[i][j][1] + bi1;
                float h2 = acc[i][j][2] + bi0, h3 = acc[i][j][3] + bi1;
                Zs[lr0 * 68 + c] = f2tf(h0); Zs[lr0 * 68 + c + 1] = f2tf(h1);
                Zs[lr1 * 68 + c] = f2tf(h2); Zs[lr1 * 68 + c + 1] = f2tf(h3);
                if (r0 < M)
                    *reinterpret_cast<float2*>(h_out + (size_t)r0 * HID + c) = make_float2(h0, h1);
                if (r1 < M)
                    *reinterpret_cast<float2*>(h_out + (size_t)r1 * HID + c) = make_float2(h2, h3);
            }
        }
    }
    __syncthreads();

    // --- stage 2: [u_pos | u_self] = h @ [Wp1|Ws1] ---
    {
        const int mW = (wid >> 2) * 64;
        const int nW = (wid & 3) * 32;
        float acc[4][4][4];
#pragma unroll
        for (int i = 0; i < 4; i++)
#pragma unroll
            for (int j = 0; j < 4; j++)
#pragma unroll
                for (int q = 0; q < 4; q++) acc[i][j][q] = 0.f;
#pragma unroll
        for (int ks = 0; ks < 8; ks++) {
            uint32_t a[4][4], b[4][2];
#pragma unroll
            for (int i = 0; i < 4; i++) {
                int r0 = mW + i * 16 + g;
                a[i][0] = Zs[r0 * 68 + ks * 8 + tg];
                a[i][1] = Zs[(r0 + 8) * 68 + ks * 8 + tg];
                a[i][2] = Zs[r0 * 68 + ks * 8 + tg + 4];
                a[i][3] = Zs[(r0 + 8) * 68 + ks * 8 + tg + 4];
            }
#pragma unroll
            for (int j = 0; j < 4; j++) {
                b[j][0] = W13[(ks * 8 + tg) * 136 + nW + j * 8 + g];
                b[j][1] = W13[(ks * 8 + tg + 4) * 136 + nW + j * 8 + g];
            }
#pragma unroll
            for (int i = 0; i < 4; i++)
#pragma unroll
                for (int j = 0; j < 4; j++)
                    mma8(acc[i][j], a[i], b[j]);
        }
        __syncthreads();
#pragma unroll
        for (int i = 0; i < 4; i++) {
            int lr0 = mW + i * 16 + g, lr1 = lr0 + 8;
            int r0 = rowBase + lr0, r1 = rowBase + lr1;
#pragma unroll
            for (int j = 0; j < 4; j++) {
                int c = nW + j * 8 + tg * 2;
                if (c < 64) {
                    float bi0 = __ldg(bp1 + c), bi1 = __ldg(bp1 + c + 1);
                    upos[lr0 * 65 + c]     = fmaxf(acc[i][j][0] + bi0, 0.f);
                    upos[lr0 * 65 + c + 1] = fmaxf(acc[i][j][1] + bi1, 0.f);
                    upos[lr1 * 65 + c]     = fmaxf(acc[i][j][2] + bi0, 0.f);
                    upos[lr1 * 65 + c + 1] = fmaxf(acc[i][j][3] + bi1, 0.f);
                } else {
                    int cc = c - 64;
                    float bi0 = __ldg(bs1 + cc), bi1 = __ldg(bs1 + cc + 1);
                    float o0 = fmaxf(acc[i][j][0] + bi0, 0.f);
                    float o1 = fmaxf(acc[i][j][1] + bi1, 0.f);
                    float o2 = fmaxf(acc[i][j][2] + bi0, 0.f);
                    float o3 = fmaxf(acc[i][j][3] + bi1, 0.f);
                    if (r0 < M)
                        *reinterpret_cast<float2*>(uself + (size_t)r0 * HID + cc) = make_float2(o0, o1);
                    if (r1 < M)
                        *reinterpret_cast<float2*>(uself + (size_t)r1 * HID + cc) = make_float2(o2, o3);
                }
            }
        }
    }
    __syncthreads();

    // --- pos head: pos = upos @ Wp2 + bp2 ---
    if (tid < 128) {
        int r = rowBase + tid;
        if (r < M) {
            float p0 = __ldg(bp2), p1 = __ldg(bp2 + 1);
#pragma unroll
            for (int k = 0; k < HID; k++) {
                float v = upos[tid * 65 + k];
                p0 = fmaf(v, __ldg(Wp2 + k * 2), p0);
                p1 = fmaf(v, __ldg(Wp2 + k * 2 + 1), p1);
            }
            pos_out[(size_t)r * 2]     = p0;
            pos_out[(size_t)r * 2 + 1] = p1;
        }
    }
}

// ---------------- BatchNorm statistics (deterministic 2-stage) ----------
__global__ void bn_stage1(const float* __restrict__ z)
{
    const int c = threadIdx.x;
    const int b = blockIdx.x;
    const int r0 = b * 100;
    float s = 0.f, ss = 0.f;
    for (int r = r0; r < r0 + 100; r++) {
        float v = z[(size_t)r * HID + c];
        s += v; ss += v * v;
    }
    g_part[b * 128 + c] = s;
    g_part[b * 128 + 64 + c] = ss;
}

// parallel stage 2: one block per channel, 128 threads reduce 500 partials
__global__ void bn_stage2(const float* __restrict__ gamma, const float* __restrict__ beta)
{
    const int c = blockIdx.x;      // 64
    const int t = threadIdx.x;     // 128
    __shared__ float sh[256];
    float s = 0.f, ss = 0.f;
    for (int b = t; b < 500; b += 128) {
        s  += g_part[b * 128 + c];
        ss += g_part[b * 128 + 64 + c];
    }
    sh[t] = s; sh[128 + t] = ss;
    __syncthreads();
    for (int o = 64; o > 0; o >>= 1) {
        if (t < o) { sh[t] += sh[t + o]; sh[128 + t] += sh[128 + t + o]; }
        __syncthreads();
    }
    if (t == 0) {
        float mu = sh[0] / (float)NSPOT;
        float var = sh[128] / (float)NSPOT - mu * mu;
        float rstd = rsqrtf(var + BN_EPS);
        float sc = gamma[c] * rstd;
        g_sc[c] = sc;
        g_sh[c] = beta[c] - mu * sc;
    }
}

// ---------------- edge aggregation ---------------------------------------
__global__ void zero_scratch()
{
    int i = blockIdx.x * blockDim.x + threadIdx.x;
    if (i < NSPOT * HID) g_agg[i] = 0.f;
    if (i < NSPOT) g_cnt[i] = 0;
}

__global__ void scatter_h(const float* __restrict__ h, const int* __restrict__ ei)
{
    long t = (long)blockIdx.x * blockDim.x + threadIdx.x;
    if (t >= (long)NEDGE * 16) return;
    int e = (int)(t >> 4), p = (int)(t & 15);
    int src = __ldg(ei + e);
    int dst = __ldg(ei + NEDGE + e);
    float4 v = *reinterpret_cast<const float4*>(h + (size_t)src * HID + p * 4);
    float* a = g_agg + (size_t)dst * HID + p * 4;
    if (p == 0) atomicAdd(&g_cnt[dst], 1);
    asm volatile("red.global.add.v4.f32 [%0], {%1,%2,%3,%4};"
                 :: "l"(a), "f"(v.x), "f"(v.y), "f"(v.z), "f"(v.w) : "memory");
}

// ---------------- launch ---------------------------------------------------
extern "C" void kernel_launch(void* const* d_in, const int* in_sizes, int n_in,
                              void* d_out, int out_size)
{
    const float* x     = (const float*)d_in[0];
    const int*   ei    = (const int*)  d_in[1];
    const float* W1    = (const float*)d_in[2];
    const float* b1    = (const float*)d_in[3];
    const float* gamma = (const float*)d_in[4];
    const float* beta  = (const float*)d_in[5];
    const float* W2    = (const float*)d_in[6];
    const float* b2    = (const float*)d_in[7];
    const float* Wp1   = (const float*)d_in[8];
    const float* bp1   = (const float*)d_in[9];
    const float* Wp2   = (const float*)d_in[10];
    const float* bp2   = (const float*)d_in[11];
    const float* Ws1   = (const float*)d_in[12];
    const float* bs1   = (const float*)d_in[13];
    const float* Ws2   = (const float*)d_in[14];
    const float* bs2   = (const float*)d_in[15];
    const float* We1   = (const float*)d_in[16];
    const float* be1   = (const float*)d_in[17];
    const float* We2   = (const float*)d_in[18];
    const float* be2   = (const float*)d_in[19];

    float* out = (float*)d_out;
    float* h_out   = out;
    float* pos_out = out + (size_t)NSPOT * HID;
    float* xs_out  = pos_out + (size_t)NSPOT * 2;
    float* xn_out  = xs_out + (size_t)NSPOT * NGENE;

    float* zp;   cudaGetSymbolAddress((void**)&zp, g_z);
    float* usp;  cudaGetSymbolAddress((void**)&usp, g_uself);
    float* aggp; cudaGetSymbolAddress((void**)&aggp, g_agg);

    const int MB = (NSPOT + 127) / 128;   // 391
    dim3 gN64(1, MB);
    dim3 gBig((NGENE + 127) / 128, MB);

    constexpr int SMEM1 = (2 * 128 * 36 + 2 * 32 * 72) * 4;             // 55296
    constexpr int SMEMF = (128 * 68 + 64 * 72 + 64 * 136) * 4;          // 88064
    cudaFuncSetAttribute(gemm1_db, cudaFuncAttributeMaxDynamicSharedMemorySize, SMEM1);
    cudaFuncSetAttribute(fused_enc, cudaFuncAttributeMaxDynamicSharedMemorySize, SMEMF);

    // 1. z = x @ W1 + b1  (K=2000, cp.async double-buffered)
    gemm1_db<<<gN64, 256, SMEM1>>>(x, W1, b1, zp, NSPOT, HID, NGENE);
    // 2. BN stats -> scale/shift (stage2 parallelized)
    bn_stage1<<<500, 64>>>(zp);
    bn_stage2<<<64, 128>>>(gamma, beta);
    // 3. zero agg scratch
    zero_scratch<<<(NSPOT * HID + 255) / 256, 256>>>();
    // 4. fused encoder tail: h, pos, u_self
    fused_enc<<<MB, 256, SMEMF>>>(zp, W2, b2, Wp1, bp1, Ws1, bs1, Wp2, bp2,
                                  h_out, pos_out, usp, NSPOT);
    // 5. neighbor aggregation (6th launch -> ncu capture slot)
    {
        long tot = (long)NEDGE * 16;
        scatter_h<<<(int)((tot + 255) / 256), 256>>>(h_out, ei);
    }
    // 6. xs = u_self @ Ws2 + bs2
    gemm_tf32<128, 128, 32, false, 0><<<gBig, 256>>>(usp, Ws2, bs2, xs_out,
                                                     NSPOT, NGENE, HID);
    // 7. u_nb = relu(mean(agg) @ We1 + be1) -> g_z
    gemm_tf32<128, 64, 32, true, 2><<<gN64, 256>>>(aggp, We1, be1, zp,
                                                   NSPOT, HID, HID);
    // 8. xn = u_nb @ We2 + be2
    gemm_tf32<128, 128, 32, false, 0><<<gBig, 256>>>(zp, We2, be2, xn_out,
                                                     NSPOT, NGENE, HID);

    (void)in_sizes; (void)n_in; (void)out_size;
}

// round 8
// speedup vs baseline: 2.0126x; 1.4011x over previous
#include <cuda_runtime.h>
#include <cstdint>

#define NSPOT 50000
#define NGENE 2000
#define HID   64
#define NEDGE 800000
#define BN_EPS 1e-5f

// ---------------- device scratch (no allocation allowed) ----------------
__device__ float g_z[NSPOT * HID];        // raw z, later reused for u_nb
__device__ float g_uself[NSPOT * HID];    // relu(h@Ws1+bs1)
__device__ float g_agg[NSPOT * HID];      // neighbor raw sums
__device__ int   g_cnt[NSPOT];
__device__ float g_part[500 * 128];
__device__ float g_sc[HID];               // gamma * rstd
__device__ float g_sh[HID];               // beta - mean * gamma * rstd
__device__ unsigned g_bnctr;              // last-block counter (wraps to 0)

// ---------------- tf32 helpers ------------------------------------------
__device__ __forceinline__ uint32_t f2tf(float f) {
    uint32_t r; asm("cvt.rna.tf32.f32 %0, %1;" : "=r"(r) : "f"(f)); return r;
}
__device__ __forceinline__ void mma8(float* c, const uint32_t* a, const uint32_t* b) {
    asm volatile(
        "mma.sync.aligned.m16n8k8.row.col.f32.tf32.tf32.f32 "
        "{%0,%1,%2,%3}, {%4,%5,%6,%7}, {%8,%9}, {%0,%1,%2,%3};"
        : "+f"(c[0]), "+f"(c[1]), "+f"(c[2]), "+f"(c[3])
        : "r"(a[0]), "r"(a[1]), "r"(a[2]), "r"(a[3]), "r"(b[0]), "r"(b[1]));
}
__device__ __forceinline__ void cpa16(uint32_t s, const void* g, bool pred) {
    int sz = pred ? 16 : 0;
    asm volatile("cp.async.cg.shared.global [%0], [%1], 16, %2;"
                 :: "r"(s), "l"(g), "r"(sz));
}

// ============ generic cp.async double-buffered TF32 GEMM ================
// BM=128, BK=32, BN = 64 or 128. C = A@B + bias. zfill handles ragged M/N/K.
template<int BN, bool RELU>
__global__ __launch_bounds__(256)
void gemm_db(const float* __restrict__ A, const float* __restrict__ B,
             const float* __restrict__ bias, float* __restrict__ C,
             int M, int N, int K)
{
    constexpr int BM = 128, BK = 32;
    constexpr int ASTR = BK + 4;             // 36
    constexpr int BSTR = BN + 8;
    constexpr int BCH  = BN / 4;             // float4 chunks per B row
    constexpr int STAGE = BM * ASTR + BK * BSTR;
    constexpr int WARPS_N = BN / 32;
    constexpr int WARPS_M = 8 / WARPS_N;
    constexpr int WM = BM / WARPS_M;
    constexpr int MT = WM / 16;

    extern __shared__ __align__(16) float dsm[];

    const int tid = threadIdx.x;
    const int lane = tid & 31, wid = tid >> 5;
    const int g = lane >> 2, tg = lane & 3;
    const int rowBase = blockIdx.y * BM;
    const int colBase = blockIdx.x * BN;
    const int mW = (wid / WARPS_N) * WM;
    const int nW = (wid % WARPS_N) * 32;

    float acc[MT][4][4];
#pragma unroll
    for (int i = 0; i < MT; i++)
#pragma unroll
        for (int j = 0; j < 4; j++)
#pragma unroll
            for (int q = 0; q < 4; q++) acc[i][j][q] = 0.f;

    const int KT = (K + BK - 1) / BK;

    auto loadTiles = [&](int buf, int k0) {
        float* Ab = dsm + buf * STAGE;
        float* Bb = Ab + BM * ASTR;
#pragma unroll
        for (int ii = 0; ii < 4; ii++) {              // A: 1024 float4 chunks
            int i = tid + ii * 256;
            int m = i >> 3, k4 = (i & 7) * 4;
            int r = rowBase + m, gk = k0 + k4;
            cpa16((uint32_t)__cvta_generic_to_shared(Ab + m * ASTR + k4),
                  A + (size_t)r * K + gk, (r < M) && (gk < K));
        }
#pragma unroll
        for (int ii = 0; ii < (BK * BCH) / 256; ii++) {   // B chunks
            int i = tid + ii * 256;
            int kk = i / BCH, n4 = (i % BCH) * 4;
            int gk = k0 + kk, c = colBase + n4;
            cpa16((uint32_t)__cvta_generic_to_shared(Bb + kk * BSTR + n4),
                  B + (size_t)gk * N + c, (gk < K) && (c < N));
        }
    };

    loadTiles(0, 0);
    asm volatile("cp.async.commit_group;");
    int buf = 0;
    for (int kt = 0; kt < KT; kt++) {
        if (kt + 1 < KT) loadTiles(buf ^ 1, (kt + 1) * BK);
        asm volatile("cp.async.commit_group;");
        asm volatile("cp.async.wait_group 1;");
        __syncthreads();
        const float* Ab = dsm + buf * STAGE;
        const float* Bb = Ab + BM * ASTR;
#pragma unroll
        for (int ks = 0; ks < BK / 8; ks++) {
            uint32_t a[MT][4], b[4][2];
#pragma unroll
            for (int i = 0; i < MT; i++) {
                int r0 = mW + i * 16 + g;
                a[i][0] = f2tf(Ab[r0 * ASTR + ks * 8 + tg]);
                a[i][1] = f2tf(Ab[(r0 + 8) * ASTR + ks * 8 + tg]);
                a[i][2] = f2tf(Ab[r0 * ASTR + ks * 8 + tg + 4]);
                a[i][3] = f2tf(Ab[(r0 + 8) * ASTR + ks * 8 + tg + 4]);
            }
#pragma unroll
            for (int j = 0; j < 4; j++) {
                b[j][0] = f2tf(Bb[(ks * 8 + tg) * BSTR + nW + j * 8 + g]);
                b[j][1] = f2tf(Bb[(ks * 8 + tg + 4) * BSTR + nW + j * 8 + g]);
            }
#pragma unroll
            for (int i = 0; i < MT; i++)
#pragma unroll
                for (int j = 0; j < 4; j++)
                    mma8(acc[i][j], a[i], b[j]);
        }
        __syncthreads();
        buf ^= 1;
    }

#pragma unroll
    for (int i = 0; i < MT; i++) {
        int r0 = rowBase + mW + i * 16 + g;
        int r1 = r0 + 8;
#pragma unroll
        for (int j = 0; j < 4; j++) {
            int c = colBase + nW + j * 8 + tg * 2;
            if (c >= N) continue;
            float bi0 = __ldg(bias + c), bi1 = __ldg(bias + c + 1);
            if (r0 < M) {
                float o0 = acc[i][j][0] + bi0, o1 = acc[i][j][1] + bi1;
                if (RELU) { o0 = fmaxf(o0, 0.f); o1 = fmaxf(o1, 0.f); }
                *reinterpret_cast<float2*>(C + (size_t)r0 * N + c) = make_float2(o0, o1);
            }
            if (r1 < M) {
                float o2 = acc[i][j][2] + bi0, o3 = acc[i][j][3] + bi1;
                if (RELU) { o2 = fmaxf(o2, 0.f); o3 = fmaxf(o3, 0.f); }
                *reinterpret_cast<float2*>(C + (size_t)r1 * N + c) = make_float2(o2, o3);
            }
        }
    }
}

// ======== generic TF32 GEMM (single-buffered, static smem) ===============
// AMODE: 0 = none, 2 = per-row 1/cnt on A.  (proven; used for we1 small gemm)
template<int BM, int BN, int BK, bool RELU, int AMODE>
__global__ __launch_bounds__(256)
void gemm_tf32(const float* __restrict__ A, const float* __restrict__ B,
               const float* __restrict__ bias, float* __restrict__ C,
               int M, int N, int K)
{
    constexpr int WARPS_N = BN / 32;
    constexpr int WARPS_M = 8 / WARPS_N;
    constexpr int WM = BM / WARPS_M;
    constexpr int MT = WM / 16;
    constexpr int NT = 4;
    constexpr int ASTR = BK + 4;
    constexpr int BSTR = BN + 8;

    __shared__ __align__(16) uint32_t As[BM * ASTR];
    __shared__ __align__(16) uint32_t Bs[BK * BSTR];

    const int tid = threadIdx.x;
    const int lane = tid & 31, wid = tid >> 5;
    const int g = lane >> 2, tg = lane & 3;
    const int rowBase = blockIdx.y * BM;
    const int colBase = blockIdx.x * BN;
    const int mW = (wid / WARPS_N) * WM;
    const int nW = (wid % WARPS_N) * 32;

    float acc[MT][NT][4];
#pragma unroll
    for (int i = 0; i < MT; i++)
#pragma unroll
        for (int j = 0; j < NT; j++)
#pragma unroll
            for (int q = 0; q < 4; q++) acc[i][j][q] = 0.f;

    for (int k0 = 0; k0 < K; k0 += BK) {
#pragma unroll 2
        for (int i = tid; i < BM * (BK / 4); i += 256) {
            int m = i / (BK / 4), k4 = (i % (BK / 4)) * 4;
            int r = rowBase + m;
            uint4 v = {0u, 0u, 0u, 0u};
            if (r < M) {
                float4 f = *reinterpret_cast<const float4*>(A + (size_t)r * K + k0 + k4);
                if (AMODE == 2) {
                    float inv = 1.0f / fmaxf((float)__ldg(&g_cnt[r]), 1.0f);
                    f.x *= inv; f.y *= inv; f.z *= inv; f.w *= inv;
                }
                v.x = f2tf(f.x); v.y = f2tf(f.y); v.z = f2tf(f.z); v.w = f2tf(f.w);
            }
            *reinterpret_cast<uint4*>(&As[m * ASTR + k4]) = v;
        }
#pragma unroll 2
        for (int i = tid; i < BK * (BN / 4); i += 256) {
            int kk = i / (BN / 4), n4 = (i % (BN / 4)) * 4;
            int c = colBase + n4;
            uint4 v = {0u, 0u, 0u, 0u};
            if (c < N) {
                float4 f = *reinterpret_cast<const float4*>(B + (size_t)(k0 + kk) * N + c);
                v.x = f2tf(f.x); v.y = f2tf(f.y); v.z = f2tf(f.z); v.w = f2tf(f.w);
            }
            *reinterpret_cast<uint4*>(&Bs[kk * BSTR + n4]) = v;
        }
        __syncthreads();
#pragma unroll
        for (int ks = 0; ks < BK / 8; ks++) {
            uint32_t a[MT][4], b[NT][2];
#pragma unroll
            for (int i = 0; i < MT; i++) {
                int r0 = mW + i * 16 + g;
                a[i][0] = As[r0 * ASTR + ks * 8 + tg];
                a[i][1] = As[(r0 + 8) * ASTR + ks * 8 + tg];
                a[i][2] = As[r0 * ASTR + ks * 8 + tg + 4];
                a[i][3] = As[(r0 + 8) * ASTR + ks * 8 + tg + 4];
            }
#pragma unroll
            for (int j = 0; j < NT; j++) {
                b[j][0] = Bs[(ks * 8 + tg) * BSTR + nW + j * 8 + g];
                b[j][1] = Bs[(ks * 8 + tg + 4) * BSTR + nW + j * 8 + g];
            }
#pragma unroll
            for (int i = 0; i < MT; i++)
#pragma unroll
                for (int j = 0; j < NT; j++)
                    mma8(acc[i][j], a[i], b[j]);
        }
        __syncthreads();
    }

#pragma unroll
    for (int i = 0; i < MT; i++) {
        int r0 = rowBase + mW + i * 16 + g;
        int r1 = r0 + 8;
#pragma unroll
        for (int j = 0; j < NT; j++) {
            int c = colBase + nW + j * 8 + tg * 2;
            if (c >= N) continue;
            float bi0 = __ldg(bias + c), bi1 = __ldg(bias + c + 1);
            if (r0 < M) {
                float o0 = acc[i][j][0] + bi0, o1 = acc[i][j][1] + bi1;
                if (RELU) { o0 = fmaxf(o0, 0.f); o1 = fmaxf(o1, 0.f); }
                *reinterpret_cast<float2*>(C + (size_t)r0 * N + c) = make_float2(o0, o1);
            }
            if (r1 < M) {
                float o2 = acc[i][j][2] + bi0, o3 = acc[i][j][3] + bi1;
                if (RELU) { o2 = fmaxf(o2, 0.f); o3 = fmaxf(o3, 0.f); }
                *reinterpret_cast<float2*>(C + (size_t)r1 * N + c) = make_float2(o2, o3);
            }
        }
    }
}

// ======== fused encoder tail: BNReLU(z)@W2 -> h ; heads ; pos ============
__global__ __launch_bounds__(256)
void fused_enc(const float* __restrict__ z,
               const float* __restrict__ W2,  const float* __restrict__ b2,
               const float* __restrict__ Wp1, const float* __restrict__ bp1,
               const float* __restrict__ Ws1, const float* __restrict__ bs1,
               const float* __restrict__ Wp2, const float* __restrict__ bp2,
               float* __restrict__ h_out, float* __restrict__ pos_out,
               float* __restrict__ uself, int M)
{
    extern __shared__ __align__(16) uint32_t fsm[];
    uint32_t* Zs  = fsm;                  // 128 x 68 (A layout, tf32)
    uint32_t* W2s = Zs + 128 * 68;        // 64 x 72  (B layout)
    uint32_t* W13 = W2s + 64 * 72;        // 64 x 136 (B layout: Wp1|Ws1)
    float* upos = reinterpret_cast<float*>(W13);   // reuse: 128 x 65

    const int tid = threadIdx.x;
    const int lane = tid & 31, wid = tid >> 5;
    const int g = lane >> 2, tg = lane & 3;
    const int rowBase = blockIdx.x * 128;

#pragma unroll
    for (int ii = 0; ii < 8; ii++) {
        int i = tid + ii * 256;
        int m = i >> 4, k4 = (i & 15) * 4;
        int r = rowBase + m;
        uint4 v = {0u, 0u, 0u, 0u};
        if (r < M) {
            float4 f = *reinterpret_cast<const float4*>(z + (size_t)r * HID + k4);
            f.x = fmaxf(fmaf(f.x, g_sc[k4+0], g_sh[k4+0]), 0.f);
            f.y = fmaxf(fmaf(f.y, g_sc[k4+1], g_sh[k4+1]), 0.f);
            f.z = fmaxf(fmaf(f.z, g_sc[k4+2], g_sh[k4+2]), 0.f);
            f.w = fmaxf(fmaf(f.w, g_sc[k4+3], g_sh[k4+3]), 0.f);
            v.x = f2tf(f.x); v.y = f2tf(f.y); v.z = f2tf(f.z); v.w = f2tf(f.w);
        }
        *reinterpret_cast<uint4*>(&Zs[m * 68 + k4]) = v;
    }
#pragma unroll
    for (int ii = 0; ii < 4; ii++) {
        int i = tid + ii * 256;
        int kk = i >> 4, n4 = (i & 15) * 4;
        float4 f = *reinterpret_cast<const float4*>(W2 + kk * HID + n4);
        uint4 v; v.x = f2tf(f.x); v.y = f2tf(f.y); v.z = f2tf(f.z); v.w = f2tf(f.w);
        *reinterpret_cast<uint4*>(&W2s[kk * 72 + n4]) = v;
    }
#pragma unroll
    for (int ii = 0; ii < 8; ii++) {
        int i = tid + ii * 256;
        int kk = i >> 5, n4 = (i & 31) * 4;
        const float* src = (n4 < 64) ? (Wp1 + kk * HID + n4) : (Ws1 + kk * HID + n4 - 64);
        float4 f = *reinterpret_cast<const float4*>(src);
        uint4 v; v.x = f2tf(f.x); v.y = f2tf(f.y); v.z = f2tf(f.z); v.w = f2tf(f.w);
        *reinterpret_cast<uint4*>(&W13[kk * 136 + n4]) = v;
    }
    __syncthreads();

    // --- stage 1: h = Zs @ W2 + b2 ---
    {
        const int mW = (wid >> 1) * 32;
        const int nW = (wid & 1) * 32;
        float acc[2][4][4];
#pragma unroll
        for (int i = 0; i < 2; i++)
#pragma unroll
            for (int j = 0; j < 4; j++)
#pragma unroll
                for (int q = 0; q < 4; q++) acc[i][j][q] = 0.f;
#pragma unroll
        for (int ks = 0; ks < 8; ks++) {
            uint32_t a[2][4], b[4][2];
#pragma unroll
            for (int i = 0; i < 2; i++) {
                int r0 = mW + i * 16 + g;
                a[i][0] = Zs[r0 * 68 + ks * 8 + tg];
                a[i][1] = Zs[(r0 + 8) * 68 + ks * 8 + tg];
                a[i][2] = Zs[r0 * 68 + ks * 8 + tg + 4];
                a[i][3] = Zs[(r0 + 8) * 68 + ks * 8 + tg + 4];
            }
#pragma unroll
            for (int j = 0; j < 4; j++) {
                b[j][0] = W2s[(ks * 8 + tg) * 72 + nW + j * 8 + g];
                b[j][1] = W2s[(ks * 8 + tg + 4) * 72 + nW + j * 8 + g];
            }
#pragma unroll
            for (int i = 0; i < 2; i++)
#pragma unroll
                for (int j = 0; j < 4; j++)
                    mma8(acc[i][j], a[i], b[j]);
        }
        __syncthreads();
#pragma unroll
        for (int i = 0; i < 2; i++) {
            int lr0 = mW + i * 16 + g, lr1 = lr0 + 8;
            int r0 = rowBase + lr0, r1 = rowBase + lr1;
#pragma unroll
            for (int j = 0; j < 4; j++) {
                int c = nW + j * 8 + tg * 2;
                float bi0 = __ldg(b2 + c), bi1 = __ldg(b2 + c + 1);
                float h0 = acc[i][j][0] + bi0, h1 = acc[i][j][1] + bi1;
                float h2 = acc[i][j][2] + bi0, h3 = acc[i][j][3] + bi1;
                Zs[lr0 * 68 + c] = f2tf(h0); Zs[lr0 * 68 + c + 1] = f2tf(h1);
                Zs[lr1 * 68 + c] = f2tf(h2); Zs[lr1 * 68 + c + 1] = f2tf(h3);
                if (r0 < M)
                    *reinterpret_cast<float2*>(h_out + (size_t)r0 * HID + c) = make_float2(h0, h1);
                if (r1 < M)
                    *reinterpret_cast<float2*>(h_out + (size_t)r1 * HID + c) = make_float2(h2, h3);
            }
        }
    }
    __syncthreads();

    // --- stage 2: [u_pos | u_self] = h @ [Wp1|Ws1] ---
    {
        const int mW = (wid >> 2) * 64;
        const int nW = (wid & 3) * 32;
        float acc[4][4][4];
#pragma unroll
        for (int i = 0; i < 4; i++)
#pragma unroll
            for (int j = 0; j < 4; j++)
#pragma unroll
                for (int q = 0; q < 4; q++) acc[i][j][q] = 0.f;
#pragma unroll
        for (int ks = 0; ks < 8; ks++) {
            uint32_t a[4][4], b[4][2];
#pragma unroll
            for (int i = 0; i < 4; i++) {
                int r0 = mW + i * 16 + g;
                a[i][0] = Zs[r0 * 68 + ks * 8 + tg];
                a[i][1] = Zs[(r0 + 8) * 68 + ks * 8 + tg];
                a[i][2] = Zs[r0 * 68 + ks * 8 + tg + 4];
                a[i][3] = Zs[(r0 + 8) * 68 + ks * 8 + tg + 4];
            }
#pragma unroll
            for (int j = 0; j < 4; j++) {
                b[j][0] = W13[(ks * 8 + tg) * 136 + nW + j * 8 + g];
                b[j][1] = W13[(ks * 8 + tg + 4) * 136 + nW + j * 8 + g];
            }
#pragma unroll
            for (int i = 0; i < 4; i++)
#pragma unroll
                for (int j = 0; j < 4; j++)
                    mma8(acc[i][j], a[i], b[j]);
        }
        __syncthreads();
#pragma unroll
        for (int i = 0; i < 4; i++) {
            int lr0 = mW + i * 16 + g, lr1 = lr0 + 8;
            int r0 = rowBase + lr0, r1 = rowBase + lr1;
#pragma unroll
            for (int j = 0; j < 4; j++) {
                int c = nW + j * 8 + tg * 2;
                if (c < 64) {
                    float bi0 = __ldg(bp1 + c), bi1 = __ldg(bp1 + c + 1);
                    upos[lr0 * 65 + c]     = fmaxf(acc[i][j][0] + bi0, 0.f);
                    upos[lr0 * 65 + c + 1] = fmaxf(acc[i][j][1] + bi1, 0.f);
                    upos[lr1 * 65 + c]     = fmaxf(acc[i][j][2] + bi0, 0.f);
                    upos[lr1 * 65 + c + 1] = fmaxf(acc[i][j][3] + bi1, 0.f);
                } else {
                    int cc = c - 64;
                    float bi0 = __ldg(bs1 + cc), bi1 = __ldg(bs1 + cc + 1);
                    float o0 = fmaxf(acc[i][j][0] + bi0, 0.f);
                    float o1 = fmaxf(acc[i][j][1] + bi1, 0.f);
                    float o2 = fmaxf(acc[i][j][2] + bi0, 0.f);
                    float o3 = fmaxf(acc[i][j][3] + bi1, 0.f);
                    if (r0 < M)
                        *reinterpret_cast<float2*>(uself + (size_t)r0 * HID + cc) = make_float2(o0, o1);
                    if (r1 < M)
                        *reinterpret_cast<float2*>(uself + (size_t)r1 * HID + cc) = make_float2(o2, o3);
                }
            }
        }
    }
    __syncthreads();

    // --- pos head: pos = upos @ Wp2 + bp2 ---
    if (tid < 128) {
        int r = rowBase + tid;
        if (r < M) {
            float p0 = __ldg(bp2), p1 = __ldg(bp2 + 1);
#pragma unroll
            for (int k = 0; k < HID; k++) {
                float v = upos[tid * 65 + k];
                p0 = fmaf(v, __ldg(Wp2 + k * 2), p0);
                p1 = fmaf(v, __ldg(Wp2 + k * 2 + 1), p1);
            }
            pos_out[(size_t)r * 2]     = p0;
            pos_out[(size_t)r * 2 + 1] = p1;
        }
    }
}

// ---------------- single-kernel BatchNorm stats (last-block reduce) ------
__global__ __launch_bounds__(256)
void bn_fused(const float* __restrict__ z,
              const float* __restrict__ gamma, const float* __restrict__ beta)
{
    __shared__ float sh1[4][64], sh2[4][64];
    __shared__ unsigned done;
    const int t = threadIdx.x;
    const int c = t & 63, q = t >> 6;          // 4 row-groups x 64 channels
    const int b = blockIdx.x;                  // 500 blocks x 100 rows

    float s = 0.f, ss = 0.f;
    int r0 = b * 100 + q * 25;
    for (int r = r0; r < r0 + 25; r++) {
        float v = z[(size_t)r * HID + c];
        s += v; ss += v * v;
    }
    sh1[q][c] = s; sh2[q][c] = ss;
    __syncthreads();
    if (q == 0) {
        s  = sh1[0][c] + sh1[1][c] + sh1[2][c] + sh1[3][c];
        ss = sh2[0][c] + sh2[1][c] + sh2[2][c] + sh2[3][c];
        g_part[b * 128 + c]      = s;
        g_part[b * 128 + 64 + c] = ss;
    }
    __threadfence();
    __syncthreads();
    if (t == 0) done = atomicInc(&g_bnctr, 499);   // wraps to 0 at 500
    __syncthreads();
    if (done == 499) {
        float s2 = 0.f, ss2 = 0.f;
        for (int bb = q; bb < 500; bb += 4) {       // fixed order -> deterministic
            s2  += g_part[bb * 128 + c];
            ss2 += g_part[bb * 128 + 64 + c];
        }
        sh1[q][c] = s2; sh2[q][c] = ss2;
        __syncthreads();
        if (q == 0) {
            float S  = sh1[0][c] + sh1[1][c] + sh1[2][c] + sh1[3][c];
            float SS = sh2[0][c] + sh2[1][c] + sh2[2][c] + sh2[3][c];
            float mu = S / (float)NSPOT;
            float var = SS / (float)NSPOT - mu * mu;
            float rstd = rsqrtf(var + BN_EPS);
            float sc = gamma[c] * rstd;
            g_sc[c] = sc;
            g_sh[c] = beta[c] - mu * sc;
        }
    }
}

// ---------------- edge aggregation ---------------------------------------
__global__ void scatter_h(const float* __restrict__ h, const int* __restrict__ ei)
{
    long t = (long)blockIdx.x * blockDim.x + threadIdx.x;
    if (t >= (long)NEDGE * 16) return;
    int e = (int)(t >> 4), p = (int)(t & 15);
    int src = __ldg(ei + e);
    int dst = __ldg(ei + NEDGE + e);
    float4 v = *reinterpret_cast<const float4*>(h + (size_t)src * HID + p * 4);
    float* a = g_agg + (size_t)dst * HID + p * 4;
    if (p == 0) atomicAdd(&g_cnt[dst], 1);
    asm volatile("red.global.add.v4.f32 [%0], {%1,%2,%3,%4};"
                 :: "l"(a), "f"(v.x), "f"(v.y), "f"(v.z), "f"(v.w) : "memory");
}

// ---------------- launch ---------------------------------------------------
extern "C" void kernel_launch(void* const* d_in, const int* in_sizes, int n_in,
                              void* d_out, int out_size)
{
    const float* x     = (const float*)d_in[0];
    const int*   ei    = (const int*)  d_in[1];
    const float* W1    = (const float*)d_in[2];
    const float* b1    = (const float*)d_in[3];
    const float* gamma = (const float*)d_in[4];
    const float* beta  = (const float*)d_in[5];
    const float* W2    = (const float*)d_in[6];
    const float* b2    = (const float*)d_in[7];
    const float* Wp1   = (const float*)d_in[8];
    const float* bp1   = (const float*)d_in[9];
    const float* Wp2   = (const float*)d_in[10];
    const float* bp2   = (const float*)d_in[11];
    const float* Ws1   = (const float*)d_in[12];
    const float* bs1   = (const float*)d_in[13];
    const float* Ws2   = (const float*)d_in[14];
    const float* bs2   = (const float*)d_in[15];
    const float* We1   = (const float*)d_in[16];
    const float* be1   = (const float*)d_in[17];
    const float* We2   = (const float*)d_in[18];
    const float* be2   = (const float*)d_in[19];

    float* out = (float*)d_out;
    float* h_out   = out;
    float* pos_out = out + (size_t)NSPOT * HID;
    float* xs_out  = pos_out + (size_t)NSPOT * 2;
    float* xn_out  = xs_out + (size_t)NSPOT * NGENE;

    float* zp;   cudaGetSymbolAddress((void**)&zp, g_z);
    float* usp;  cudaGetSymbolAddress((void**)&usp, g_uself);
    float* aggp; cudaGetSymbolAddress((void**)&aggp, g_agg);
    int*   cntp; cudaGetSymbolAddress((void**)&cntp, g_cnt);

    const int MB = (NSPOT + 127) / 128;   // 391
    dim3 gN64(1, MB);
    dim3 gBig((NGENE + 127) / 128, MB);   // 16 x 391

    constexpr int SMEM_DB64  = 2 * (128 * 36 + 32 * 72)  * 4;   // 55296
    constexpr int SMEM_DB128 = 2 * (128 * 36 + 32 * 136) * 4;   // 71680
    constexpr int SMEMF      = (128 * 68 + 64 * 72 + 64 * 136) * 4;  // 88064
    cudaFuncSetAttribute(gemm_db<64, false>,
                         cudaFuncAttributeMaxDynamicSharedMemorySize, SMEM_DB64);
    cudaFuncSetAttribute(gemm_db<128, false>,
                         cudaFuncAttributeMaxDynamicSharedMemorySize, SMEM_DB128);
    cudaFuncSetAttribute(fused_enc, cudaFuncAttributeMaxDynamicSharedMemorySize, SMEMF);

    // zero agg scratch via memset nodes (not kernel launches)
    cudaMemsetAsync(aggp, 0, (size_t)NSPOT * HID * sizeof(float));
    cudaMemsetAsync(cntp, 0, (size_t)NSPOT * sizeof(int));

    // k1. z = x @ W1 + b1  (K=2000, cp.async double-buffered)
    gemm_db<64, false><<<gN64, 256, SMEM_DB64>>>(x, W1, b1, zp, NSPOT, HID, NGENE);
    // k2. BN stats -> scale/shift (single kernel, last-block reduce)
    bn_fused<<<500, 256>>>(zp, gamma, beta);
    // k3. fused encoder tail: h, pos, u_self
    fused_enc<<<MB, 256, SMEMF>>>(zp, W2, b2, Wp1, bp1, Ws1, bs1, Wp2, bp2,
                                  h_out, pos_out, usp, NSPOT);
    // k4. xs = u_self @ Ws2 + bs2   <-- ncu capture slot
    gemm_db<128, false><<<gBig, 256, SMEM_DB128>>>(usp, Ws2, bs2, xs_out,
                                                   NSPOT, NGENE, HID);
    // k5. neighbor aggregation
    {
        long tot = (long)NEDGE * 16;
        scatter_h<<<(int)((tot + 255) / 256), 256>>>(h_out, ei);
    }
    // k6. u_nb = relu(mean(agg) @ We1 + be1) -> g_z
    gemm_tf32<128, 64, 32, true, 2><<<gN64, 256>>>(aggp, We1, be1, zp,
                                                   NSPOT, HID, HID);
    // k7. xn = u_nb @ We2 + be2
    gemm_db<128, false><<<gBig, 256, SMEM_DB128>>>(zp, We2, be2, xn_out,
                                                   NSPOT, NGENE, HID);

    (void)in_sizes; (void)n_in; (void)out_size;
}